// round 11
// baseline (speedup 1.0000x reference)
#include <cuda_runtime.h>
#include <cuda_bf16.h>
#include <cstdint>

// EuclideanCodebook on GB300 (base sm_103 target):
//   pre-tiled/pre-swizzled bf16 layout -> cp.async.bulk (2 DMA per stage) ->
//   HMMA mma.sync GEMM (CTA 256x128, warp 64x64) -> per-slice top-4 ->
//   R1-exact fp32 rescore -> gather + loss.
//
//  x:     (32768, 1280) fp32   d_in[0]
//  embed: (4096, 1280)  fp32   d_in[1]
//  out:   [quantized 32768*1280 | indices 32768 | loss 1] fp32

#define NT 32768
#define D  1280
#define NC 4096

#define BM 256
#define BN 128
#define BK 64                    // bf16 per k-stage
#define KITERS (D / BK)          // 20
#define N_TILES (NC / BN)        // 32
#define M_TILES (NT / BM)        // 128
#define MARGIN 6.0e-3f
#define A_TILE_BYTES (BM * BK * 2)   // 32768
#define B_TILE_BYTES (BN * BK * 2)   // 16384
#define CHUNKS (D / 8)           // 160 16B-chunks per row

// ---------------- static device scratch ----------------
// staged layouts: [tile][kt][row][chunk perm] contiguous blocks
__device__ __align__(128) unsigned char g_A[(size_t)NT * D * 2];  // 84 MB
__device__ __align__(128) unsigned char g_B[(size_t)NC * D * 2];  // 10.5 MB
__device__ float g_esq[NC];
__device__ ulonglong4 g_top4[(size_t)N_TILES * NT];               // 33.5 MB
__device__ float g_loss;

// ---------------- smem layout (dynamic) ----------------
#define STAGE_SZ  49152                  // A 32KB + B 16KB
#define OFF_A(s)  ((s) * STAGE_SZ)
#define OFF_B(s)  ((s) * STAGE_SZ + A_TILE_BYTES)
#define SC_PITCH  133                    // score buffer aliases stage smem
#define OFF_ESQ   (3 * STAGE_SZ)         // 147456
#define OFF_MBAR  (OFF_ESQ + 512)
#define SMEM_SZ   (OFF_MBAR + 64)        // 148032 (1 CTA/SM)

// ---------------- PTX helpers ----------------
__device__ __forceinline__ uint32_t smem_u32(const void* p) {
    uint32_t a;
    asm("{ .reg .u64 t; cvta.to.shared.u64 t, %1; cvt.u32.u64 %0, t; }"
        : "=r"(a) : "l"(p));
    return a;
}
#define MBAR_INIT(mb, n) \
    asm volatile("mbarrier.init.shared.b64 [%0], %1;" :: "r"((uint32_t)(mb)), "r"((uint32_t)(n)) : "memory")
#define MBAR_EXPECT(mb, bytes) \
    asm volatile("mbarrier.arrive.expect_tx.shared.b64 _, [%0], %1;" \
                 :: "r"((uint32_t)(mb)), "r"((uint32_t)(bytes)) : "memory")
#define MBAR_WAIT(mb, ph) do {                                                          \
    uint32_t _m = (uint32_t)(mb), _p = (uint32_t)(ph), _d;                              \
    asm volatile("{ .reg .pred p; mbarrier.try_wait.parity.shared.b64 p, [%1], %2;"     \
                 " selp.b32 %0,1,0,p; }" : "=r"(_d) : "r"(_m), "r"(_p) : "memory");     \
    if (!_d) {                                                                          \
        asm volatile("{ .reg .pred P1; WL_%=: mbarrier.try_wait.parity.shared.b64 P1, [%0], %1;" \
                     " @P1 bra.uni WD_%=; bra.uni WL_%=; WD_%=: }"                      \
                     :: "r"(_m), "r"(_p) : "memory");                                   \
    } } while (0)
__device__ __forceinline__ void bulk_g2s(uint32_t dst, const void* src,
                                         uint32_t bytes, uint32_t mbar) {
    asm volatile("cp.async.bulk.shared::cluster.global.mbarrier::complete_tx::bytes "
                 "[%0], [%1], %2, [%3];"
                 :: "r"(dst), "l"(src), "r"(bytes), "r"(mbar) : "memory");
}

__device__ __forceinline__ void ldm_x4(uint32_t* r, uint32_t addr) {
    asm volatile("ldmatrix.sync.aligned.m8n8.x4.shared.b16 {%0,%1,%2,%3}, [%4];"
                 : "=r"(r[0]), "=r"(r[1]), "=r"(r[2]), "=r"(r[3]) : "r"(addr));
}
__device__ __forceinline__ void mma_bf16(float* d, const uint32_t* a,
                                         uint32_t b0, uint32_t b1) {
    asm volatile("mma.sync.aligned.m16n8k16.row.col.f32.bf16.bf16.f32 "
                 "{%0,%1,%2,%3}, {%4,%5,%6,%7}, {%8,%9}, {%0,%1,%2,%3};"
                 : "+f"(d[0]), "+f"(d[1]), "+f"(d[2]), "+f"(d[3])
                 : "r"(a[0]), "r"(a[1]), "r"(a[2]), "r"(a[3]), "r"(b0), "r"(b1));
}

__device__ __forceinline__ unsigned long long pack_key(float s, int idx) {
    uint32_t fb = __float_as_uint(s);
    uint32_t key = (fb & 0x80000000u) ? ~fb : (fb | 0x80000000u);
    return ((unsigned long long)key << 32) |
           (unsigned long long)(0xFFFFFFFFu - (uint32_t)idx);
}
__device__ __forceinline__ float unpack_score(unsigned long long pk) {
    uint32_t k = (uint32_t)(pk >> 32);
    return __uint_as_float((k & 0x80000000u) ? (k ^ 0x80000000u) : ~k);
}

// ---------------------------------------------------------------------------
// fp32 -> bf16 staging into tiled/swizzled layout (rptLog: rows per tile).
// ---------------------------------------------------------------------------
__global__ void conv_kernel(const float* __restrict__ src,
                            unsigned char* __restrict__ dst, int nchunks,
                            int rptLog) {
    int i = blockIdx.x * blockDim.x + threadIdx.x;
    if (i >= nchunks) return;
    const int t = i / CHUNKS, c = i - t * CHUNKS;
    const int kt = c >> 3, ch = c & 7;
    const int row = t & ((1 << rptLog) - 1), tile = t >> rptLog;

    const float4* s = (const float4*)(src + (size_t)t * D + c * 8);
    float4 a = s[0], b = s[1];
    __nv_bfloat162 h0 = __float22bfloat162_rn(make_float2(a.x, a.y));
    __nv_bfloat162 h1 = __float22bfloat162_rn(make_float2(a.z, a.w));
    __nv_bfloat162 h2 = __float22bfloat162_rn(make_float2(b.x, b.y));
    __nv_bfloat162 h3 = __float22bfloat162_rn(make_float2(b.z, b.w));
    uint4 v;
    v.x = *(uint32_t*)&h0; v.y = *(uint32_t*)&h1;
    v.z = *(uint32_t*)&h2; v.w = *(uint32_t*)&h3;

    size_t off = ((size_t)(tile * KITERS + kt) << (rptLog + 7)) + (row << 7)
               + ((ch ^ (row & 7)) << 4);
    *(uint4*)(dst + off) = v;
}

// ---------------------------------------------------------------------------
// prep: exact e_sq per code + loss init
// ---------------------------------------------------------------------------
__global__ void prep_kernel(const float* __restrict__ embed) {
    const int code = blockIdx.x;
    const float4* e = (const float4*)(embed + (size_t)code * D);
    float s = 0.f;
    for (int i = threadIdx.x; i < D / 4; i += blockDim.x) {
        float4 v = e[i];
        s += v.x * v.x + v.y * v.y + v.z * v.z + v.w * v.w;
    }
    #pragma unroll
    for (int o = 16; o > 0; o >>= 1) s += __shfl_down_sync(0xffffffffu, s, o);
    __shared__ float red[4];
    if ((threadIdx.x & 31) == 0) red[threadIdx.x >> 5] = s;
    __syncthreads();
    if (threadIdx.x == 0) {
        g_esq[code] = red[0] + red[1] + red[2] + red[3];
        if (code == 0) g_loss = 0.f;
    }
}

// ---------------------------------------------------------------------------
// HMMA bf16 GEMM (bulk-DMA staged) + per-slice top-4
// grid (N_TILES, M_TILES) x 256 threads. Warp 4x2: warp tile 64(m) x 64(n).
// ---------------------------------------------------------------------------
__global__ __launch_bounds__(256, 1) void gemm_kernel() {
    extern __shared__ char smem[];
    const uint32_t sb = smem_u32(smem);
    const int tid = threadIdx.x;
    const int warp = tid >> 5, lane = tid & 31;
    const int warp_m = warp >> 1, warp_n = warp & 1;
    const int codeBase = blockIdx.x * BN;
    const int tokBase  = blockIdx.y * BM;

    float* esq_s = (float*)(smem + OFF_ESQ);
    if (tid < BN) esq_s[tid] = g_esq[codeBase + tid];

    const unsigned char* Ab = g_A + ((size_t)blockIdx.y * KITERS << 15);
    const unsigned char* Bb = g_B + ((size_t)blockIdx.x * KITERS << 14);

    if (tid == 0) {
        #pragma unroll
        for (int s = 0; s < 3; s++) MBAR_INIT(sb + OFF_MBAR + s * 8, 1);
    }
    __syncthreads();

    if (tid == 0) {
        #pragma unroll
        for (int s = 0; s < 2; s++) {
            MBAR_EXPECT(sb + OFF_MBAR + s * 8, STAGE_SZ);
            bulk_g2s(sb + OFF_A(s), Ab + ((size_t)s << 15), A_TILE_BYTES,
                     sb + OFF_MBAR + s * 8);
            bulk_g2s(sb + OFF_B(s), Bb + ((size_t)s << 14), B_TILE_BYTES,
                     sb + OFF_MBAR + s * 8);
        }
    }

    // ldmatrix address pieces (SW128: xor by row&7 == l15&7)
    const int l15 = lane & 15;
    const int colsel = lane >> 4;
    const int sw = l15 & 7;
    uint32_t aRow[4], bRow[4], ckx[4];
    #pragma unroll
    for (int mt = 0; mt < 4; mt++) aRow[mt] = (warp_m * 64 + mt * 16 + l15) * 128;
    #pragma unroll
    for (int nh = 0; nh < 4; nh++) bRow[nh] = (warp_n * 64 + nh * 16 + l15) * 128;
    #pragma unroll
    for (int kh = 0; kh < 4; kh++) ckx[kh] = (uint32_t)(((2 * kh + colsel) ^ sw) << 4);

    float acc[4][8][4];
    #pragma unroll
    for (int mt = 0; mt < 4; mt++)
        #pragma unroll
        for (int nt = 0; nt < 8; nt++)
            #pragma unroll
            for (int i = 0; i < 4; i++) acc[mt][nt][i] = 0.f;

    int slot = 0, slot2 = 2;
    int phase[3] = {0, 0, 0};
    for (int kt = 0; kt < KITERS; kt++) {
        __syncthreads();                   // all warps done reading slot2's old data
        if (kt + 2 < KITERS && tid == 0) {
            MBAR_EXPECT(sb + OFF_MBAR + slot2 * 8, STAGE_SZ);
            bulk_g2s(sb + OFF_A(slot2), Ab + ((size_t)(kt + 2) << 15), A_TILE_BYTES,
                     sb + OFF_MBAR + slot2 * 8);
            bulk_g2s(sb + OFF_B(slot2), Bb + ((size_t)(kt + 2) << 14), B_TILE_BYTES,
                     sb + OFF_MBAR + slot2 * 8);
        }
        MBAR_WAIT(sb + OFF_MBAR + slot * 8, phase[slot]);
        phase[slot] ^= 1;

        const uint32_t ab = sb + OFF_A(slot), bb = sb + OFF_B(slot);
        #pragma unroll
        for (int kh = 0; kh < 4; kh++) {
            uint32_t a[4][4], b[4][4];
            #pragma unroll
            for (int mt = 0; mt < 4; mt++) ldm_x4(a[mt], ab + aRow[mt] + ckx[kh]);
            #pragma unroll
            for (int nh = 0; nh < 4; nh++) ldm_x4(b[nh], bb + bRow[nh] + ckx[kh]);
            #pragma unroll
            for (int mt = 0; mt < 4; mt++)
                #pragma unroll
                for (int nt = 0; nt < 8; nt++)
                    mma_bf16(acc[mt][nt], a[mt],
                             b[nt >> 1][nt & 1], b[nt >> 1][(nt & 1) + 2]);
        }
        if (++slot == 3) slot = 0;
        if (++slot2 == 3) slot2 = 0;
    }
    __syncthreads();   // stage buffers dead -> reuse as score buffer

    // scores -> smem [256][SC_PITCH]
    float* sc = (float*)smem;
    const int rq = lane >> 2;
    const int cq = (lane & 3) * 2;
    #pragma unroll
    for (int mt = 0; mt < 4; mt++) {
        const int r = warp_m * 64 + mt * 16 + rq;
        #pragma unroll
        for (int nt = 0; nt < 8; nt++) {
            const int c = warp_n * 64 + nt * 8 + cq;
            sc[r * SC_PITCH + c]           = 2.f * acc[mt][nt][0] - esq_s[c];
            sc[r * SC_PITCH + c + 1]       = 2.f * acc[mt][nt][1] - esq_s[c + 1];
            sc[(r + 8) * SC_PITCH + c]     = 2.f * acc[mt][nt][2] - esq_s[c];
            sc[(r + 8) * SC_PITCH + c + 1] = 2.f * acc[mt][nt][3] - esq_s[c + 1];
        }
    }
    __syncthreads();

    // one thread per token (256): packed top-4 over this 128-code slice
    {
        const float* row = sc + tid * SC_PITCH;
        unsigned long long t0 = 0ull, t1 = 0ull, t2 = 0ull, t3 = 0ull;
        #pragma unroll 4
        for (int j = 0; j < BN; j++) {
            unsigned long long pk = pack_key(row[j], codeBase + j);
            if (pk > t0)      { t3 = t2; t2 = t1; t1 = t0; t0 = pk; }
            else if (pk > t1) { t3 = t2; t2 = t1; t1 = pk; }
            else if (pk > t2) { t3 = t2; t2 = pk; }
            else if (pk > t3) { t3 = pk; }
        }
        g_top4[(size_t)blockIdx.x * NT + tokBase + tid] =
            make_ulonglong4(t0, t1, t2, t3);
    }
}

// ---------------------------------------------------------------------------
// merge + R1-exact sequential-k fp32 rescore + gather + loss; warp per token.
// ---------------------------------------------------------------------------
__global__ __launch_bounds__(256) void merge_kernel(const float* __restrict__ x,
                                                    const float* __restrict__ embed,
                                                    float* __restrict__ out,
                                                    long long out_size) {
    const int warp = threadIdx.x >> 5, lane = threadIdx.x & 31;
    const int t = blockIdx.x * 8 + warp;

    ulonglong4 v = g_top4[(size_t)lane * NT + t];   // 32 slices == 32 lanes

    unsigned long long m = v.x;
    #pragma unroll
    for (int o = 16; o > 0; o >>= 1) {
        unsigned long long mo = __shfl_xor_sync(0xffffffffu, m, o);
        if (mo > m) m = mo;
    }
    const float thr = unpack_score(m) - MARGIN;

    const float4* xr4 = (const float4*)(x + (size_t)t * D);

    float xs = 0.f;
    #pragma unroll
    for (int i = 0; i < 10; i++) {
        float4 a = xr4[lane + i * 32];
        xs += a.x * a.x + a.y * a.y + a.z * a.z + a.w * a.w;
    }
    #pragma unroll
    for (int o = 16; o > 0; o >>= 1) xs += __shfl_xor_sync(0xffffffffu, xs, o);

    unsigned long long bestKey = 0ull;
    unsigned long long cand[4] = {v.x, v.y, v.z, v.w};
    #pragma unroll
    for (int slot = 0; slot < 4; slot++) {
        bool act = (unpack_score(cand[slot]) >= thr);
        if (__ballot_sync(0xffffffffu, act)) {
            if (act) {
                int idx = (int)(0xFFFFFFFFu - (uint32_t)cand[slot]);
                const float4* er4 = (const float4*)(embed + (size_t)idx * D);
                float d = 0.f;
                for (int i = 0; i < D / 4; i++) {       // strict ascending k
                    float4 a = xr4[i];
                    float4 b = er4[i];
                    d = fmaf(a.x, b.x, d);
                    d = fmaf(a.y, b.y, d);
                    d = fmaf(a.z, b.z, d);
                    d = fmaf(a.w, b.w, d);
                }
                float s = 2.0f * d - g_esq[idx];
                unsigned long long k = pack_key(s, idx);
                if (k > bestKey) bestKey = k;
            }
        }
    }
    #pragma unroll
    for (int o = 16; o > 0; o >>= 1) {
        unsigned long long ko = __shfl_xor_sync(0xffffffffu, bestKey, o);
        if (ko > bestKey) bestKey = ko;
    }
    const int bestI = (int)(0xFFFFFFFFu - (uint32_t)bestKey);
    const float bestS = unpack_score(bestKey);

    if (lane == 0) {
        if (out_size >= (long long)NT * D + NT)
            out[(size_t)NT * D + t] = (float)bestI;
        atomicAdd(&g_loss, xs - bestS);
    }
    const float4* er = (const float4*)(embed + (size_t)bestI * D);
    float4* o = (float4*)(out + (size_t)t * D);
    #pragma unroll
    for (int i = 0; i < 10; i++) o[lane + i * 32] = er[lane + i * 32];
}

__global__ void loss_kernel(float* __restrict__ out, long long out_size) {
    if (out_size >= (long long)NT * D + NT + 1)
        out[(size_t)NT * D + NT] = g_loss / (float)((long long)NT * D);
}

// ---------------------------------------------------------------------------
extern "C" void kernel_launch(void* const* d_in, const int* in_sizes, int n_in,
                              void* d_out, int out_size) {
    const float* x     = (const float*)d_in[0];
    const float* embed = (const float*)d_in[1];
    float* out = (float*)d_out;

    static int smem_set = 0;
    if (!smem_set) {
        cudaFuncSetAttribute(gemm_kernel, cudaFuncAttributeMaxDynamicSharedMemorySize, SMEM_SZ);
        smem_set = 1;
    }

    unsigned char* gA;
    unsigned char* gB;
    cudaGetSymbolAddress((void**)&gA, g_A);
    cudaGetSymbolAddress((void**)&gB, g_B);

    conv_kernel<<<(NT * CHUNKS + 255) / 256, 256>>>(x, gA, NT * CHUNKS, 8);
    conv_kernel<<<(NC * CHUNKS + 255) / 256, 256>>>(embed, gB, NC * CHUNKS, 7);
    prep_kernel<<<NC, 128>>>(embed);
    gemm_kernel<<<dim3(N_TILES, M_TILES), 256, SMEM_SZ>>>();
    merge_kernel<<<NT / 8, 256>>>(x, embed, out, (long long)out_size);
    loss_kernel<<<1, 1>>>(out, (long long)out_size);
}

// round 12
// speedup vs baseline: 1.1163x; 1.1163x over previous
#include <cuda_runtime.h>
#include <cuda_bf16.h>
#include <cstdint>

// EuclideanCodebook on GB300 (base sm_103 target):
//   fp8 e4m3 screening GEMM (mma.sync.m16n8k32, R8 skeleton: CTA 128x128,
//   warp 64x32, 3-stage bulk-DMA, 2 CTA/SM) -> per-slice top-4 ->
//   margin (0.02) R1-exact fp32 rescore -> gather + loss.
//
//  x:     (32768, 1280) fp32   d_in[0]
//  embed: (4096, 1280)  fp32   d_in[1]
//  out:   [quantized 32768*1280 | indices 32768 | loss 1] fp32

#define NT 32768
#define D  1280
#define NC 4096

#define BM 128
#define BN 128
#define BK 128                   // fp8 elems per k-stage (128 B rows, SW128)
#define KITERS (D / BK)          // 10
#define N_TILES (NC / BN)        // 32
#define M_TILES (NT / BM)        // 256
#define MARGIN 0.02f             // fp8 screening noise sigma ~2.8e-3
#define SCALE 128.0f
#define INV2  1.220703125e-4f    // 2 / (SCALE*SCALE)
#define TILE_BYTES (BM * BK)     // 16384
#define CHUNKS (D / 16)          // 80 16B-chunks per row

// ---------------- static device scratch ----------------
// staged fp8 layouts: [tile][kt][row 128][chunk perm] 16KB contiguous blocks
__device__ __align__(128) unsigned char g_A[(size_t)NT * D];      // 42 MB
__device__ __align__(128) unsigned char g_B[(size_t)NC * D];      // 5.2 MB
__device__ float g_esq[NC];
__device__ ulonglong4 g_top4[(size_t)N_TILES * NT];               // 33.5 MB
__device__ float g_loss;

// ---------------- smem layout (dynamic) ----------------
#define STAGE_SZ  32768                  // A 16KB + B 16KB
#define OFF_A(s)  ((s) * STAGE_SZ)
#define OFF_B(s)  ((s) * STAGE_SZ + TILE_BYTES)
#define SC_PITCH  137                    // score buffer aliases stage smem
#define OFF_ESQ   (3 * STAGE_SZ)         // 98304
#define OFF_MBAR  (OFF_ESQ + 512)
#define SMEM_SZ   (OFF_MBAR + 64)        // 98880 (x2 CTA <= 228KB)

// ---------------- PTX helpers ----------------
__device__ __forceinline__ uint32_t smem_u32(const void* p) {
    uint32_t a;
    asm("{ .reg .u64 t; cvta.to.shared.u64 t, %1; cvt.u32.u64 %0, t; }"
        : "=r"(a) : "l"(p));
    return a;
}
#define MBAR_INIT(mb, n) \
    asm volatile("mbarrier.init.shared.b64 [%0], %1;" :: "r"((uint32_t)(mb)), "r"((uint32_t)(n)) : "memory")
#define MBAR_EXPECT(mb, bytes) \
    asm volatile("mbarrier.arrive.expect_tx.shared.b64 _, [%0], %1;" \
                 :: "r"((uint32_t)(mb)), "r"((uint32_t)(bytes)) : "memory")
#define MBAR_WAIT(mb, ph) do {                                                          \
    uint32_t _m = (uint32_t)(mb), _p = (uint32_t)(ph), _d;                              \
    asm volatile("{ .reg .pred p; mbarrier.try_wait.parity.shared.b64 p, [%1], %2;"     \
                 " selp.b32 %0,1,0,p; }" : "=r"(_d) : "r"(_m), "r"(_p) : "memory");     \
    if (!_d) {                                                                          \
        asm volatile("{ .reg .pred P1; WL_%=: mbarrier.try_wait.parity.shared.b64 P1, [%0], %1;" \
                     " @P1 bra.uni WD_%=; bra.uni WL_%=; WD_%=: }"                      \
                     :: "r"(_m), "r"(_p) : "memory");                                   \
    } } while (0)
__device__ __forceinline__ void bulk_g2s(uint32_t dst, const void* src,
                                         uint32_t bytes, uint32_t mbar) {
    asm volatile("cp.async.bulk.shared::cluster.global.mbarrier::complete_tx::bytes "
                 "[%0], [%1], %2, [%3];"
                 :: "r"(dst), "l"(src), "r"(bytes), "r"(mbar) : "memory");
}

__device__ __forceinline__ void ldm_x4(uint32_t* r, uint32_t addr) {
    asm volatile("ldmatrix.sync.aligned.m8n8.x4.shared.b16 {%0,%1,%2,%3}, [%4];"
                 : "=r"(r[0]), "=r"(r[1]), "=r"(r[2]), "=r"(r[3]) : "r"(addr));
}
__device__ __forceinline__ void mma_fp8(float* d, const uint32_t* a,
                                        uint32_t b0, uint32_t b1) {
    asm volatile("mma.sync.aligned.m16n8k32.row.col.f32.e4m3.e4m3.f32 "
                 "{%0,%1,%2,%3}, {%4,%5,%6,%7}, {%8,%9}, {%0,%1,%2,%3};"
                 : "+f"(d[0]), "+f"(d[1]), "+f"(d[2]), "+f"(d[3])
                 : "r"(a[0]), "r"(a[1]), "r"(a[2]), "r"(a[3]), "r"(b0), "r"(b1));
}

__device__ __forceinline__ unsigned long long pack_key(float s, int idx) {
    uint32_t fb = __float_as_uint(s);
    uint32_t key = (fb & 0x80000000u) ? ~fb : (fb | 0x80000000u);
    return ((unsigned long long)key << 32) |
           (unsigned long long)(0xFFFFFFFFu - (uint32_t)idx);
}
__device__ __forceinline__ float unpack_score(unsigned long long pk) {
    uint32_t k = (uint32_t)(pk >> 32);
    return __uint_as_float((k & 0x80000000u) ? (k ^ 0x80000000u) : ~k);
}

__device__ __forceinline__ unsigned short fp8pair(float lo, float hi) {
    unsigned short r;
    asm("cvt.rn.satfinite.e4m3x2.f32 %0, %1, %2;" : "=h"(r) : "f"(hi), "f"(lo));
    return r;   // lo -> low byte, hi -> high byte
}

// ---------------------------------------------------------------------------
// fp32 -> fp8 (x SCALE) staging into tiled/swizzled layout (128-row tiles).
// One thread per 16-byte chunk (16 elements).
// ---------------------------------------------------------------------------
__global__ void conv_kernel(const float* __restrict__ src,
                            unsigned char* __restrict__ dst, int nchunks) {
    int i = blockIdx.x * blockDim.x + threadIdx.x;
    if (i >= nchunks) return;
    const int t = i / CHUNKS, c = i - t * CHUNKS;
    const int kt = c >> 3, ch = c & 7;
    const int row = t & 127, tile = t >> 7;

    const float4* s = (const float4*)(src + (size_t)t * D + c * 16);
    float4 f0 = s[0], f1 = s[1], f2 = s[2], f3 = s[3];

    unsigned int w0 = (unsigned int)fp8pair(f0.x * SCALE, f0.y * SCALE)
                    | ((unsigned int)fp8pair(f0.z * SCALE, f0.w * SCALE) << 16);
    unsigned int w1 = (unsigned int)fp8pair(f1.x * SCALE, f1.y * SCALE)
                    | ((unsigned int)fp8pair(f1.z * SCALE, f1.w * SCALE) << 16);
    unsigned int w2 = (unsigned int)fp8pair(f2.x * SCALE, f2.y * SCALE)
                    | ((unsigned int)fp8pair(f2.z * SCALE, f2.w * SCALE) << 16);
    unsigned int w3 = (unsigned int)fp8pair(f3.x * SCALE, f3.y * SCALE)
                    | ((unsigned int)fp8pair(f3.z * SCALE, f3.w * SCALE) << 16);

    uint4 v = make_uint4(w0, w1, w2, w3);
    size_t off = ((size_t)(tile * KITERS + kt) << 14) + (row << 7)
               + ((ch ^ (row & 7)) << 4);
    *(uint4*)(dst + off) = v;
}

// ---------------------------------------------------------------------------
// prep: exact e_sq per code + loss init
// ---------------------------------------------------------------------------
__global__ void prep_kernel(const float* __restrict__ embed) {
    const int code = blockIdx.x;
    const float4* e = (const float4*)(embed + (size_t)code * D);
    float s = 0.f;
    for (int i = threadIdx.x; i < D / 4; i += blockDim.x) {
        float4 v = e[i];
        s += v.x * v.x + v.y * v.y + v.z * v.z + v.w * v.w;
    }
    #pragma unroll
    for (int o = 16; o > 0; o >>= 1) s += __shfl_down_sync(0xffffffffu, s, o);
    __shared__ float red[4];
    if ((threadIdx.x & 31) == 0) red[threadIdx.x >> 5] = s;
    __syncthreads();
    if (threadIdx.x == 0) {
        g_esq[code] = red[0] + red[1] + red[2] + red[3];
        if (code == 0) g_loss = 0.f;
    }
}

// ---------------------------------------------------------------------------
// fp8 HMMA GEMM (bulk-DMA staged) + per-slice top-4
// grid (N_TILES, M_TILES) x 256 threads. Warp 2x4: warp tile 64(m) x 32(n).
// ---------------------------------------------------------------------------
__global__ __launch_bounds__(256, 2) void gemm_kernel() {
    extern __shared__ char smem[];
    const uint32_t sb = smem_u32(smem);
    const int tid = threadIdx.x;
    const int warp = tid >> 5, lane = tid & 31;
    const int warp_m = warp >> 2, warp_n = warp & 3;
    const int codeBase = blockIdx.x * BN;
    const int tokBase  = blockIdx.y * BM;

    float* esq_s = (float*)(smem + OFF_ESQ);
    if (tid < BN) esq_s[tid] = g_esq[codeBase + tid];

    const unsigned char* Ab = g_A + ((size_t)blockIdx.y * KITERS << 14);
    const unsigned char* Bb = g_B + ((size_t)blockIdx.x * KITERS << 14);

    if (tid == 0) {
        #pragma unroll
        for (int s = 0; s < 3; s++) MBAR_INIT(sb + OFF_MBAR + s * 8, 1);
    }
    __syncthreads();

    if (tid == 0) {
        #pragma unroll
        for (int s = 0; s < 2; s++) {
            MBAR_EXPECT(sb + OFF_MBAR + s * 8, STAGE_SZ);
            bulk_g2s(sb + OFF_A(s), Ab + ((size_t)s << 14), TILE_BYTES,
                     sb + OFF_MBAR + s * 8);
            bulk_g2s(sb + OFF_B(s), Bb + ((size_t)s << 14), TILE_BYTES,
                     sb + OFF_MBAR + s * 8);
        }
    }

    // ldmatrix address pieces (SW128: xor by row&7 == l15&7)
    const int l15 = lane & 15;
    const int colsel = lane >> 4;
    const int sw = l15 & 7;
    uint32_t aRow[4], bRow[2], ckx[4];
    #pragma unroll
    for (int mt = 0; mt < 4; mt++) aRow[mt] = (warp_m * 64 + mt * 16 + l15) * 128;
    #pragma unroll
    for (int nh = 0; nh < 2; nh++) bRow[nh] = (warp_n * 32 + nh * 16 + l15) * 128;
    #pragma unroll
    for (int kh = 0; kh < 4; kh++) ckx[kh] = (uint32_t)(((2 * kh + colsel) ^ sw) << 4);

    float acc[4][4][4];
    #pragma unroll
    for (int mt = 0; mt < 4; mt++)
        #pragma unroll
        for (int nt = 0; nt < 4; nt++)
            #pragma unroll
            for (int i = 0; i < 4; i++) acc[mt][nt][i] = 0.f;

    int slot = 0, slot2 = 2;
    int phase[3] = {0, 0, 0};
    for (int kt = 0; kt < KITERS; kt++) {
        __syncthreads();                   // all warps done reading slot2's old data
        if (kt + 2 < KITERS && tid == 0) {
            MBAR_EXPECT(sb + OFF_MBAR + slot2 * 8, STAGE_SZ);
            bulk_g2s(sb + OFF_A(slot2), Ab + ((size_t)(kt + 2) << 14), TILE_BYTES,
                     sb + OFF_MBAR + slot2 * 8);
            bulk_g2s(sb + OFF_B(slot2), Bb + ((size_t)(kt + 2) << 14), TILE_BYTES,
                     sb + OFF_MBAR + slot2 * 8);
        }
        MBAR_WAIT(sb + OFF_MBAR + slot * 8, phase[slot]);
        phase[slot] ^= 1;

        const uint32_t ab = sb + OFF_A(slot), bb = sb + OFF_B(slot);
        #pragma unroll
        for (int kh = 0; kh < 4; kh++) {   // each kh covers 32 B = K 32 fp8
            uint32_t a[4][4], b[2][4];
            #pragma unroll
            for (int mt = 0; mt < 4; mt++) ldm_x4(a[mt], ab + aRow[mt] + ckx[kh]);
            #pragma unroll
            for (int nh = 0; nh < 2; nh++) ldm_x4(b[nh], bb + bRow[nh] + ckx[kh]);
            #pragma unroll
            for (int mt = 0; mt < 4; mt++)
                #pragma unroll
                for (int nt = 0; nt < 4; nt++)
                    mma_fp8(acc[mt][nt], a[mt],
                            b[nt >> 1][nt & 1], b[nt >> 1][(nt & 1) + 2]);
        }
        if (++slot == 3) slot = 0;
        if (++slot2 == 3) slot2 = 0;
    }
    __syncthreads();   // stage buffers dead -> reuse as score buffer

    // scores -> smem [128][SC_PITCH]   (score = acc*2/S^2 - esq)
    float* sc = (float*)smem;
    const int rq = lane >> 2;
    const int cq = (lane & 3) * 2;
    #pragma unroll
    for (int mt = 0; mt < 4; mt++) {
        const int r = warp_m * 64 + mt * 16 + rq;
        #pragma unroll
        for (int nt = 0; nt < 4; nt++) {
            const int c = warp_n * 32 + nt * 8 + cq;
            sc[r * SC_PITCH + c]           = acc[mt][nt][0] * INV2 - esq_s[c];
            sc[r * SC_PITCH + c + 1]       = acc[mt][nt][1] * INV2 - esq_s[c + 1];
            sc[(r + 8) * SC_PITCH + c]     = acc[mt][nt][2] * INV2 - esq_s[c];
            sc[(r + 8) * SC_PITCH + c + 1] = acc[mt][nt][3] * INV2 - esq_s[c + 1];
        }
    }
    __syncthreads();

    // one thread per token: packed top-4 over this 128-code slice
    if (tid < BM) {
        const float* row = sc + tid * SC_PITCH;
        unsigned long long t0 = 0ull, t1 = 0ull, t2 = 0ull, t3 = 0ull;
        #pragma unroll 4
        for (int j = 0; j < BN; j++) {
            unsigned long long pk = pack_key(row[j], codeBase + j);
            if (pk > t0)      { t3 = t2; t2 = t1; t1 = t0; t0 = pk; }
            else if (pk > t1) { t3 = t2; t2 = t1; t1 = pk; }
            else if (pk > t2) { t3 = t2; t2 = pk; }
            else if (pk > t3) { t3 = pk; }
        }
        g_top4[(size_t)blockIdx.x * NT + tokBase + tid] =
            make_ulonglong4(t0, t1, t2, t3);
    }
}

// ---------------------------------------------------------------------------
// merge + R1-exact sequential-k fp32 rescore + gather + loss; warp per token.
// ---------------------------------------------------------------------------
__global__ __launch_bounds__(256) void merge_kernel(const float* __restrict__ x,
                                                    const float* __restrict__ embed,
                                                    float* __restrict__ out,
                                                    long long out_size) {
    const int warp = threadIdx.x >> 5, lane = threadIdx.x & 31;
    const int t = blockIdx.x * 8 + warp;

    ulonglong4 v = g_top4[(size_t)lane * NT + t];   // 32 slices == 32 lanes

    unsigned long long m = v.x;
    #pragma unroll
    for (int o = 16; o > 0; o >>= 1) {
        unsigned long long mo = __shfl_xor_sync(0xffffffffu, m, o);
        if (mo > m) m = mo;
    }
    const float thr = unpack_score(m) - MARGIN;

    const float4* xr4 = (const float4*)(x + (size_t)t * D);

    float xs = 0.f;
    #pragma unroll
    for (int i = 0; i < 10; i++) {
        float4 a = xr4[lane + i * 32];
        xs += a.x * a.x + a.y * a.y + a.z * a.z + a.w * a.w;
    }
    #pragma unroll
    for (int o = 16; o > 0; o >>= 1) xs += __shfl_xor_sync(0xffffffffu, xs, o);

    unsigned long long bestKey = 0ull;
    unsigned long long cand[4] = {v.x, v.y, v.z, v.w};
    #pragma unroll
    for (int slot = 0; slot < 4; slot++) {
        bool act = (unpack_score(cand[slot]) >= thr);
        if (__ballot_sync(0xffffffffu, act)) {
            if (act) {
                int idx = (int)(0xFFFFFFFFu - (uint32_t)cand[slot]);
                const float4* er4 = (const float4*)(embed + (size_t)idx * D);
                float d = 0.f;
                for (int i = 0; i < D / 4; i++) {       // strict ascending k
                    float4 a = xr4[i];
                    float4 b = er4[i];
                    d = fmaf(a.x, b.x, d);
                    d = fmaf(a.y, b.y, d);
                    d = fmaf(a.z, b.z, d);
                    d = fmaf(a.w, b.w, d);
                }
                float s = 2.0f * d - g_esq[idx];
                unsigned long long k = pack_key(s, idx);
                if (k > bestKey) bestKey = k;
            }
        }
    }
    #pragma unroll
    for (int o = 16; o > 0; o >>= 1) {
        unsigned long long ko = __shfl_xor_sync(0xffffffffu, bestKey, o);
        if (ko > bestKey) bestKey = ko;
    }
    const int bestI = (int)(0xFFFFFFFFu - (uint32_t)bestKey);
    const float bestS = unpack_score(bestKey);

    if (lane == 0) {
        if (out_size >= (long long)NT * D + NT)
            out[(size_t)NT * D + t] = (float)bestI;
        atomicAdd(&g_loss, xs - bestS);
    }
    const float4* er = (const float4*)(embed + (size_t)bestI * D);
    float4* o = (float4*)(out + (size_t)t * D);
    #pragma unroll
    for (int i = 0; i < 10; i++) o[lane + i * 32] = er[lane + i * 32];
}

__global__ void loss_kernel(float* __restrict__ out, long long out_size) {
    if (out_size >= (long long)NT * D + NT + 1)
        out[(size_t)NT * D + NT] = g_loss / (float)((long long)NT * D);
}

// ---------------------------------------------------------------------------
extern "C" void kernel_launch(void* const* d_in, const int* in_sizes, int n_in,
                              void* d_out, int out_size) {
    const float* x     = (const float*)d_in[0];
    const float* embed = (const float*)d_in[1];
    float* out = (float*)d_out;

    static int smem_set = 0;
    if (!smem_set) {
        cudaFuncSetAttribute(gemm_kernel, cudaFuncAttributeMaxDynamicSharedMemorySize, SMEM_SZ);
        smem_set = 1;
    }

    unsigned char* gA;
    unsigned char* gB;
    cudaGetSymbolAddress((void**)&gA, g_A);
    cudaGetSymbolAddress((void**)&gB, g_B);

    conv_kernel<<<(NT * CHUNKS + 255) / 256, 256>>>(x, gA, NT * CHUNKS);
    conv_kernel<<<(NC * CHUNKS + 255) / 256, 256>>>(embed, gB, NC * CHUNKS);
    prep_kernel<<<NC, 128>>>(embed);
    gemm_kernel<<<dim3(N_TILES, M_TILES), 256, SMEM_SZ>>>();
    merge_kernel<<<NT / 8, 256>>>(x, embed, out, (long long)out_size);
    loss_kernel<<<1, 1>>>(out, (long long)out_size);
}

// round 13
// speedup vs baseline: 1.1314x; 1.0136x over previous
#include <cuda_runtime.h>
#include <cuda_bf16.h>
#include <cstdint>

// EuclideanCodebook on GB300 (base sm_103 target):
//   fp8 e4m3 screening GEMM (mma.sync.m16n8k32, CTA 128x128, warp 64x32,
//   3-stage bulk-DMA ring with producer/consumer mbarriers — NO in-loop
//   syncthreads) -> per-slice top-4 -> margin (0.02) R1-exact fp32 rescore.
//
//  x:     (32768, 1280) fp32   d_in[0]
//  embed: (4096, 1280)  fp32   d_in[1]
//  out:   [quantized 32768*1280 | indices 32768 | loss 1] fp32

#define NT 32768
#define D  1280
#define NC 4096

#define BM 128
#define BN 128
#define BK 128                   // fp8 elems per k-stage (128 B rows, SW128)
#define KITERS (D / BK)          // 10
#define N_TILES (NC / BN)        // 32
#define M_TILES (NT / BM)        // 256
#define MARGIN 0.02f
#define SCALE 128.0f
#define INV2  1.220703125e-4f    // 2 / (SCALE*SCALE)
#define TILE_BYTES (BM * BK)     // 16384
#define CHUNKS (D / 16)          // 80 16B-chunks per row

// ---------------- static device scratch ----------------
__device__ __align__(128) unsigned char g_A[(size_t)NT * D];      // 42 MB
__device__ __align__(128) unsigned char g_B[(size_t)NC * D];      // 5.2 MB
__device__ float g_esq[NC];
__device__ ulonglong4 g_top4[(size_t)N_TILES * NT];               // 33.5 MB
__device__ float g_loss;

// ---------------- smem layout (dynamic) ----------------
#define STAGE_SZ  32768                  // A 16KB + B 16KB
#define OFF_A(s)  ((s) * STAGE_SZ)
#define OFF_B(s)  ((s) * STAGE_SZ + TILE_BYTES)
#define SC_PITCH  137                    // score buffer aliases stage smem
#define OFF_ESQ   (3 * STAGE_SZ)         // 98304
#define OFF_MBAR  (OFF_ESQ + 512)        // 3 x (full,empty) pairs, 16B each
#define MB_FULL(s)  (OFF_MBAR + (s) * 16)
#define MB_EMPTY(s) (OFF_MBAR + (s) * 16 + 8)
#define SMEM_SZ   (OFF_MBAR + 64)        // 98880 (x2 CTA <= 228KB)

// ---------------- PTX helpers ----------------
__device__ __forceinline__ uint32_t smem_u32(const void* p) {
    uint32_t a;
    asm("{ .reg .u64 t; cvta.to.shared.u64 t, %1; cvt.u32.u64 %0, t; }"
        : "=r"(a) : "l"(p));
    return a;
}
#define MBAR_INIT(mb, n) \
    asm volatile("mbarrier.init.shared.b64 [%0], %1;" :: "r"((uint32_t)(mb)), "r"((uint32_t)(n)) : "memory")
#define MBAR_EXPECT(mb, bytes) \
    asm volatile("mbarrier.arrive.expect_tx.shared.b64 _, [%0], %1;" \
                 :: "r"((uint32_t)(mb)), "r"((uint32_t)(bytes)) : "memory")
#define MBAR_ARRIVE(mb) \
    asm volatile("mbarrier.arrive.shared.b64 _, [%0];" :: "r"((uint32_t)(mb)) : "memory")
#define MBAR_WAIT(mb, ph) do {                                                          \
    uint32_t _m = (uint32_t)(mb), _p = (uint32_t)(ph), _d;                              \
    asm volatile("{ .reg .pred p; mbarrier.try_wait.parity.shared.b64 p, [%1], %2;"     \
                 " selp.b32 %0,1,0,p; }" : "=r"(_d) : "r"(_m), "r"(_p) : "memory");     \
    if (!_d) {                                                                          \
        asm volatile("{ .reg .pred P1; WL_%=: mbarrier.try_wait.parity.shared.b64 P1, [%0], %1;" \
                     " @P1 bra.uni WD_%=; bra.uni WL_%=; WD_%=: }"                      \
                     :: "r"(_m), "r"(_p) : "memory");                                   \
    } } while (0)
__device__ __forceinline__ void bulk_g2s(uint32_t dst, const void* src,
                                         uint32_t bytes, uint32_t mbar) {
    asm volatile("cp.async.bulk.shared::cluster.global.mbarrier::complete_tx::bytes "
                 "[%0], [%1], %2, [%3];"
                 :: "r"(dst), "l"(src), "r"(bytes), "r"(mbar) : "memory");
}

__device__ __forceinline__ void ldm_x4(uint32_t* r, uint32_t addr) {
    asm volatile("ldmatrix.sync.aligned.m8n8.x4.shared.b16 {%0,%1,%2,%3}, [%4];"
                 : "=r"(r[0]), "=r"(r[1]), "=r"(r[2]), "=r"(r[3]) : "r"(addr));
}
__device__ __forceinline__ void mma_fp8(float* d, const uint32_t* a,
                                        uint32_t b0, uint32_t b1) {
    asm volatile("mma.sync.aligned.m16n8k32.row.col.f32.e4m3.e4m3.f32 "
                 "{%0,%1,%2,%3}, {%4,%5,%6,%7}, {%8,%9}, {%0,%1,%2,%3};"
                 : "+f"(d[0]), "+f"(d[1]), "+f"(d[2]), "+f"(d[3])
                 : "r"(a[0]), "r"(a[1]), "r"(a[2]), "r"(a[3]), "r"(b0), "r"(b1));
}

__device__ __forceinline__ unsigned long long pack_key(float s, int idx) {
    uint32_t fb = __float_as_uint(s);
    uint32_t key = (fb & 0x80000000u) ? ~fb : (fb | 0x80000000u);
    return ((unsigned long long)key << 32) |
           (unsigned long long)(0xFFFFFFFFu - (uint32_t)idx);
}
__device__ __forceinline__ float unpack_score(unsigned long long pk) {
    uint32_t k = (uint32_t)(pk >> 32);
    return __uint_as_float((k & 0x80000000u) ? (k ^ 0x80000000u) : ~k);
}

__device__ __forceinline__ unsigned short fp8pair(float lo, float hi) {
    unsigned short r;
    asm("cvt.rn.satfinite.e4m3x2.f32 %0, %1, %2;" : "=h"(r) : "f"(hi), "f"(lo));
    return r;
}

// ---------------------------------------------------------------------------
// fp32 -> fp8 (x SCALE) staging into tiled/swizzled layout (128-row tiles).
// ---------------------------------------------------------------------------
__global__ void conv_kernel(const float* __restrict__ src,
                            unsigned char* __restrict__ dst, int nchunks) {
    int i = blockIdx.x * blockDim.x + threadIdx.x;
    if (i >= nchunks) return;
    const int t = i / CHUNKS, c = i - t * CHUNKS;
    const int kt = c >> 3, ch = c & 7;
    const int row = t & 127, tile = t >> 7;

    const float4* s = (const float4*)(src + (size_t)t * D + c * 16);
    float4 f0 = s[0], f1 = s[1], f2 = s[2], f3 = s[3];

    unsigned int w0 = (unsigned int)fp8pair(f0.x * SCALE, f0.y * SCALE)
                    | ((unsigned int)fp8pair(f0.z * SCALE, f0.w * SCALE) << 16);
    unsigned int w1 = (unsigned int)fp8pair(f1.x * SCALE, f1.y * SCALE)
                    | ((unsigned int)fp8pair(f1.z * SCALE, f1.w * SCALE) << 16);
    unsigned int w2 = (unsigned int)fp8pair(f2.x * SCALE, f2.y * SCALE)
                    | ((unsigned int)fp8pair(f2.z * SCALE, f2.w * SCALE) << 16);
    unsigned int w3 = (unsigned int)fp8pair(f3.x * SCALE, f3.y * SCALE)
                    | ((unsigned int)fp8pair(f3.z * SCALE, f3.w * SCALE) << 16);

    uint4 v = make_uint4(w0, w1, w2, w3);
    size_t off = ((size_t)(tile * KITERS + kt) << 14) + (row << 7)
               + ((ch ^ (row & 7)) << 4);
    *(uint4*)(dst + off) = v;
}

// ---------------------------------------------------------------------------
// prep: exact e_sq per code + loss init
// ---------------------------------------------------------------------------
__global__ void prep_kernel(const float* __restrict__ embed) {
    const int code = blockIdx.x;
    const float4* e = (const float4*)(embed + (size_t)code * D);
    float s = 0.f;
    for (int i = threadIdx.x; i < D / 4; i += blockDim.x) {
        float4 v = e[i];
        s += v.x * v.x + v.y * v.y + v.z * v.z + v.w * v.w;
    }
    #pragma unroll
    for (int o = 16; o > 0; o >>= 1) s += __shfl_down_sync(0xffffffffu, s, o);
    __shared__ float red[4];
    if ((threadIdx.x & 31) == 0) red[threadIdx.x >> 5] = s;
    __syncthreads();
    if (threadIdx.x == 0) {
        g_esq[code] = red[0] + red[1] + red[2] + red[3];
        if (code == 0) g_loss = 0.f;
    }
}

// ---------------------------------------------------------------------------
// fp8 HMMA GEMM: 3-stage ring, producer/consumer mbarriers, no loop syncs.
// grid (N_TILES, M_TILES) x 256 threads. Warp 2x4: warp tile 64(m) x 32(n).
// ---------------------------------------------------------------------------
__global__ __launch_bounds__(256, 2) void gemm_kernel() {
    extern __shared__ char smem[];
    const uint32_t sb = smem_u32(smem);
    const int tid = threadIdx.x;
    const int warp = tid >> 5, lane = tid & 31;
    const int warp_m = warp >> 2, warp_n = warp & 3;
    const int codeBase = blockIdx.x * BN;
    const int tokBase  = blockIdx.y * BM;

    float* esq_s = (float*)(smem + OFF_ESQ);
    if (tid < BN) esq_s[tid] = g_esq[codeBase + tid];

    const unsigned char* Ab = g_A + ((size_t)blockIdx.y * KITERS << 14);
    const unsigned char* Bb = g_B + ((size_t)blockIdx.x * KITERS << 14);

    if (tid == 0) {
        #pragma unroll
        for (int s = 0; s < 3; s++) {
            MBAR_INIT(sb + MB_FULL(s), 1);
            MBAR_INIT(sb + MB_EMPTY(s), 8);   // one arrive per warp
        }
    }
    __syncthreads();

    if (tid == 0) {
        #pragma unroll
        for (int s = 0; s < 2; s++) {
            MBAR_EXPECT(sb + MB_FULL(s), STAGE_SZ);
            bulk_g2s(sb + OFF_A(s), Ab + ((size_t)s << 14), TILE_BYTES,
                     sb + MB_FULL(s));
            bulk_g2s(sb + OFF_B(s), Bb + ((size_t)s << 14), TILE_BYTES,
                     sb + MB_FULL(s));
        }
    }

    // ldmatrix address pieces (SW128: xor by row&7 == l15&7)
    const int l15 = lane & 15;
    const int colsel = lane >> 4;
    const int sw = l15 & 7;
    uint32_t aRow[4], bRow[2], ckx[4];
    #pragma unroll
    for (int mt = 0; mt < 4; mt++) aRow[mt] = (warp_m * 64 + mt * 16 + l15) * 128;
    #pragma unroll
    for (int nh = 0; nh < 2; nh++) bRow[nh] = (warp_n * 32 + nh * 16 + l15) * 128;
    #pragma unroll
    for (int kh = 0; kh < 4; kh++) ckx[kh] = (uint32_t)(((2 * kh + colsel) ^ sw) << 4);

    float acc[4][4][4];
    #pragma unroll
    for (int mt = 0; mt < 4; mt++)
        #pragma unroll
        for (int nt = 0; nt < 4; nt++)
            #pragma unroll
            for (int i = 0; i < 4; i++) acc[mt][nt][i] = 0.f;

    int slot = 0, cph = 0;        // consumer stage + phase
    int slot2 = 2, pph = 1;       // producer stage + phase (toggles to 0 at kt=0 wrap)
    for (int kt = 0; kt < KITERS; kt++) {
        if (tid == 0 && kt + 2 < KITERS) {
            if (kt >= 1) MBAR_WAIT(sb + MB_EMPTY(slot2), pph);  // refill: old data consumed?
            MBAR_EXPECT(sb + MB_FULL(slot2), STAGE_SZ);
            bulk_g2s(sb + OFF_A(slot2), Ab + ((size_t)(kt + 2) << 14), TILE_BYTES,
                     sb + MB_FULL(slot2));
            bulk_g2s(sb + OFF_B(slot2), Bb + ((size_t)(kt + 2) << 14), TILE_BYTES,
                     sb + MB_FULL(slot2));
        }
        if (++slot2 == 3) { slot2 = 0; pph ^= 1; }

        MBAR_WAIT(sb + MB_FULL(slot), cph);

        const uint32_t ab = sb + OFF_A(slot), bb = sb + OFF_B(slot);
        #pragma unroll
        for (int kh = 0; kh < 4; kh++) {   // each kh covers 32 B = K 32 fp8
            uint32_t a[4][4], b[2][4];
            #pragma unroll
            for (int mt = 0; mt < 4; mt++) ldm_x4(a[mt], ab + aRow[mt] + ckx[kh]);
            #pragma unroll
            for (int nh = 0; nh < 2; nh++) ldm_x4(b[nh], bb + bRow[nh] + ckx[kh]);
            #pragma unroll
            for (int mt = 0; mt < 4; mt++)
                #pragma unroll
                for (int nt = 0; nt < 4; nt++)
                    mma_fp8(acc[mt][nt], a[mt],
                            b[nt >> 1][nt & 1], b[nt >> 1][(nt & 1) + 2]);
        }
        if (lane == 0) MBAR_ARRIVE(sb + MB_EMPTY(slot));   // this warp done reading
        if (++slot == 3) { slot = 0; cph ^= 1; }
    }
    __syncthreads();   // all warps done; stage buffers dead -> score buffer

    // scores -> smem [128][SC_PITCH]   (score = acc*2/S^2 - esq)
    float* sc = (float*)smem;
    const int rq = lane >> 2;
    const int cq = (lane & 3) * 2;
    #pragma unroll
    for (int mt = 0; mt < 4; mt++) {
        const int r = warp_m * 64 + mt * 16 + rq;
        #pragma unroll
        for (int nt = 0; nt < 4; nt++) {
            const int c = warp_n * 32 + nt * 8 + cq;
            sc[r * SC_PITCH + c]           = acc[mt][nt][0] * INV2 - esq_s[c];
            sc[r * SC_PITCH + c + 1]       = acc[mt][nt][1] * INV2 - esq_s[c + 1];
            sc[(r + 8) * SC_PITCH + c]     = acc[mt][nt][2] * INV2 - esq_s[c];
            sc[(r + 8) * SC_PITCH + c + 1] = acc[mt][nt][3] * INV2 - esq_s[c + 1];
        }
    }
    __syncthreads();

    // one thread per token: packed top-4 over this 128-code slice
    if (tid < BM) {
        const float* row = sc + tid * SC_PITCH;
        unsigned long long t0 = 0ull, t1 = 0ull, t2 = 0ull, t3 = 0ull;
        #pragma unroll 4
        for (int j = 0; j < BN; j++) {
            unsigned long long pk = pack_key(row[j], codeBase + j);
            if (pk > t0)      { t3 = t2; t2 = t1; t1 = t0; t0 = pk; }
            else if (pk > t1) { t3 = t2; t2 = t1; t1 = pk; }
            else if (pk > t2) { t3 = t2; t2 = pk; }
            else if (pk > t3) { t3 = pk; }
        }
        g_top4[(size_t)blockIdx.x * NT + tokBase + tid] =
            make_ulonglong4(t0, t1, t2, t3);
    }
}

// ---------------------------------------------------------------------------
// merge + R1-exact sequential-k fp32 rescore + gather + loss; warp per token.
// ---------------------------------------------------------------------------
__global__ __launch_bounds__(256) void merge_kernel(const float* __restrict__ x,
                                                    const float* __restrict__ embed,
                                                    float* __restrict__ out,
                                                    long long out_size) {
    const int warp = threadIdx.x >> 5, lane = threadIdx.x & 31;
    const int t = blockIdx.x * 8 + warp;

    ulonglong4 v = g_top4[(size_t)lane * NT + t];   // 32 slices == 32 lanes

    unsigned long long m = v.x;
    #pragma unroll
    for (int o = 16; o > 0; o >>= 1) {
        unsigned long long mo = __shfl_xor_sync(0xffffffffu, m, o);
        if (mo > m) m = mo;
    }
    const float thr = unpack_score(m) - MARGIN;

    const float4* xr4 = (const float4*)(x + (size_t)t * D);

    float xs = 0.f;
    #pragma unroll
    for (int i = 0; i < 10; i++) {
        float4 a = xr4[lane + i * 32];
        xs += a.x * a.x + a.y * a.y + a.z * a.z + a.w * a.w;
    }
    #pragma unroll
    for (int o = 16; o > 0; o >>= 1) xs += __shfl_xor_sync(0xffffffffu, xs, o);

    unsigned long long bestKey = 0ull;
    unsigned long long cand[4] = {v.x, v.y, v.z, v.w};
    #pragma unroll
    for (int slot = 0; slot < 4; slot++) {
        bool act = (unpack_score(cand[slot]) >= thr);
        if (__ballot_sync(0xffffffffu, act)) {
            if (act) {
                int idx = (int)(0xFFFFFFFFu - (uint32_t)cand[slot]);
                const float4* er4 = (const float4*)(embed + (size_t)idx * D);
                float d = 0.f;
                for (int i = 0; i < D / 4; i++) {       // strict ascending k
                    float4 a = xr4[i];
                    float4 b = er4[i];
                    d = fmaf(a.x, b.x, d);
                    d = fmaf(a.y, b.y, d);
                    d = fmaf(a.z, b.z, d);
                    d = fmaf(a.w, b.w, d);
                }
                float s = 2.0f * d - g_esq[idx];
                unsigned long long k = pack_key(s, idx);
                if (k > bestKey) bestKey = k;
            }
        }
    }
    #pragma unroll
    for (int o = 16; o > 0; o >>= 1) {
        unsigned long long ko = __shfl_xor_sync(0xffffffffu, bestKey, o);
        if (ko > bestKey) bestKey = ko;
    }
    const int bestI = (int)(0xFFFFFFFFu - (uint32_t)bestKey);
    const float bestS = unpack_score(bestKey);

    if (lane == 0) {
        if (out_size >= (long long)NT * D + NT)
            out[(size_t)NT * D + t] = (float)bestI;
        atomicAdd(&g_loss, xs - bestS);
    }
    const float4* er = (const float4*)(embed + (size_t)bestI * D);
    float4* o = (float4*)(out + (size_t)t * D);
    #pragma unroll
    for (int i = 0; i < 10; i++) o[lane + i * 32] = er[lane + i * 32];
}

__global__ void loss_kernel(float* __restrict__ out, long long out_size) {
    if (out_size >= (long long)NT * D + NT + 1)
        out[(size_t)NT * D + NT] = g_loss / (float)((long long)NT * D);
}

// ---------------------------------------------------------------------------
extern "C" void kernel_launch(void* const* d_in, const int* in_sizes, int n_in,
                              void* d_out, int out_size) {
    const float* x     = (const float*)d_in[0];
    const float* embed = (const float*)d_in[1];
    float* out = (float*)d_out;

    static int smem_set = 0;
    if (!smem_set) {
        cudaFuncSetAttribute(gemm_kernel, cudaFuncAttributeMaxDynamicSharedMemorySize, SMEM_SZ);
        smem_set = 1;
    }

    unsigned char* gA;
    unsigned char* gB;
    cudaGetSymbolAddress((void**)&gA, g_A);
    cudaGetSymbolAddress((void**)&gB, g_B);

    conv_kernel<<<(NT * CHUNKS + 255) / 256, 256>>>(x, gA, NT * CHUNKS);
    conv_kernel<<<(NC * CHUNKS + 255) / 256, 256>>>(embed, gB, NC * CHUNKS);
    prep_kernel<<<NC, 128>>>(embed);
    gemm_kernel<<<dim3(N_TILES, M_TILES), 256, SMEM_SZ>>>();
    merge_kernel<<<NT / 8, 256>>>(x, embed, out, (long long)out_size);
    loss_kernel<<<1, 1>>>(out, (long long)out_size);
}